// round 3
// baseline (speedup 1.0000x reference)
#include <cuda_runtime.h>
#include <math.h>

// ---------------- problem constants ----------------
#define T_      1024
#define H_      2048
#define I_      1024
#define E_      16
#define TWOI_   2048
#define G_      4
#define EPG_    4     // experts per group
#define TOPK_   4
#define NPAIR_  (T_*TOPK_)   // 4096
#define ROUTED_SCALE_ 2.5f

// ---------------- device scratch (no allocations allowed) ----------------
__device__ float d_gu  [(size_t)NPAIR_*TWOI_]; // routed gate_up outputs (by slot t*4+k)
__device__ float d_act [(size_t)NPAIR_*I_];    // routed silu*u*weight (by slot)
__device__ float d_yrt [(size_t)NPAIR_*H_];    // routed down outputs (by slot)
__device__ float d_sgu [(size_t)T_*TWOI_];     // shared gate_up outputs
__device__ float d_sact[(size_t)T_*I_];        // shared silu*u
__device__ float d_sy  [(size_t)T_*H_];        // shared down outputs
__device__ int   d_cnt [E_];                   // tokens per expert
__device__ int   d_tok [E_*T_];                // gather: token index per expert entry
__device__ int   d_dst [E_*T_];                // scatter: slot (t*4+k) per expert entry
__device__ float d_wslot[NPAIR_];              // routing weight per slot

// ---------------- small kernels ----------------
__global__ void zero_cnt_kernel() {
    if (threadIdx.x < E_) d_cnt[threadIdx.x] = 0;
}

// One block per token. 16 warps -> 16 expert logits (fp32 exact — routing
// decisions must not be perturbed by low precision), then thread 0 does
// grouped top-k exactly like the reference.
__global__ void router_kernel(const float* __restrict__ x,
                              const float* __restrict__ gate_w,
                              const float* __restrict__ e_bias) {
    int t = blockIdx.x;
    int warp = threadIdx.x >> 5;
    int lane = threadIdx.x & 31;
    const float* xr = x + (size_t)t * H_;
    const float* wr = gate_w + (size_t)warp * H_;
    float s = 0.f;
    for (int h = lane; h < H_; h += 32) s += xr[h] * wr[h];
    #pragma unroll
    for (int o = 16; o; o >>= 1) s += __shfl_xor_sync(0xFFFFFFFFu, s, o);
    __shared__ float logit[E_];
    if (lane == 0) logit[warp] = s;
    __syncthreads();
    if (threadIdx.x == 0) {
        float sc[E_], sb[E_];
        #pragma unroll
        for (int e = 0; e < E_; e++) {
            sc[e] = 1.f / (1.f + expf(-logit[e]));
            sb[e] = sc[e] + e_bias[e];
        }
        float gs[G_];
        #pragma unroll
        for (int g = 0; g < G_; g++) {
            float m1 = -INFINITY, m2 = -INFINITY;
            #pragma unroll
            for (int i = 0; i < EPG_; i++) {
                float v = sb[g*EPG_ + i];
                if (v > m1) { m2 = m1; m1 = v; }
                else if (v > m2) { m2 = v; }
            }
            gs[g] = m1 + m2;
        }
        int g1 = 0;
        for (int g = 1; g < G_; g++) if (gs[g] > gs[g1]) g1 = g;
        int g2 = -1;
        for (int g = 0; g < G_; g++) {
            if (g == g1) continue;
            if (g2 < 0 || gs[g] > gs[g2]) g2 = g;
        }
        float tmp[E_];
        #pragma unroll
        for (int e = 0; e < E_; e++) {
            int g = e / EPG_;
            tmp[e] = (g == g1 || g == g2) ? sb[e] : 0.f;
        }
        bool taken[E_];
        #pragma unroll
        for (int e = 0; e < E_; e++) taken[e] = false;
        int ids[TOPK_]; float wv[TOPK_]; float wsum = 0.f;
        #pragma unroll
        for (int k = 0; k < TOPK_; k++) {
            int bi = -1; float bv = -INFINITY;
            for (int e = 0; e < E_; e++) {
                if (!taken[e] && tmp[e] > bv) { bv = tmp[e]; bi = e; }
            }
            taken[bi] = true;
            ids[k] = bi;
            wv[k] = sc[bi];
            wsum += wv[k];
        }
        float inv = 1.f / wsum;
        #pragma unroll
        for (int k = 0; k < TOPK_; k++) {
            int e = ids[k];
            int pos = atomicAdd(&d_cnt[e], 1);
            d_tok[e*T_ + pos] = t;
            d_dst[e*T_ + pos] = t*TOPK_ + k;
            d_wslot[t*TOPK_ + k] = wv[k] * inv;
        }
    }
}

// ---------------- tf32 helpers ----------------
__device__ __forceinline__ unsigned f2tf32(float x) {
    unsigned y;
    asm("cvt.rna.tf32.f32 %0, %1;" : "=r"(y) : "f"(x));
    return y;
}

__device__ __forceinline__ void mma_tf32(float c[4], const unsigned a[4], const unsigned b[2]) {
    asm volatile(
        "mma.sync.aligned.m16n8k8.row.col.f32.tf32.tf32.f32 "
        "{%0,%1,%2,%3}, {%4,%5,%6,%7}, {%8,%9}, {%0,%1,%2,%3};"
        : "+f"(c[0]), "+f"(c[1]), "+f"(c[2]), "+f"(c[3])
        : "r"(a[0]), "r"(a[1]), "r"(a[2]), "r"(a[3]), "r"(b[0]), "r"(b[1]));
}

__device__ __forceinline__ void cp16(unsigned dst, const float* src, int sz) {
    asm volatile("cp.async.ca.shared.global [%0], [%1], 16, %2;"
                 :: "r"(dst), "l"(src), "r"(sz));
}

// ---------------- pipelined tensor-core TN GEMM ----------------
// C[M,N] = A[M,K] * B[N,K]^T, 128x128 tile, BK=16, 3-stage cp.async pipeline,
// 128 threads = 4 warps (2Mx2N), warp tile 64x64, tf32 mma m16n8k8 fp32-acc.
// smem rows stride 20 floats (16B aligned rows; fragment LDS conflict-free).
#define PIPE_STAGES 3
#define ROWSTRIDE   20
#define STAGE_FLTS  (128*ROWSTRIDE)           // 2560
#define SMEM_BYTES  (2*PIPE_STAGES*STAGE_FLTS*4)  // 61440

template<bool GATHER_A, bool SCATTER_C, bool EXPERT>
__global__ void __launch_bounds__(128, 2)
mma_gemm_tn(const float* __restrict__ Abase, int lda,
            const float* __restrict__ Bbase, int ldb, long strideB,
            float* __restrict__ Cbase, int ldc,
            int Mfixed, const int* __restrict__ counts,
            const int* __restrict__ gatherA,
            const int* __restrict__ scatterC,
            int K)
{
    const int e = EXPERT ? blockIdx.z : 0;
    const int M = EXPERT ? counts[e] : Mfixed;
    const int m0 = blockIdx.y * 128;
    if (m0 >= M) return;
    const int n0 = blockIdx.x * 128;
    const float* B = Bbase + (long)e * strideB;

    extern __shared__ float sm[];
    float* As = sm;
    float* Bs = sm + PIPE_STAGES*STAGE_FLTS;

    const int tid  = threadIdx.x;
    const int lane = tid & 31;
    const int warp = tid >> 5;
    const int wm   = warp >> 1;         // 0..1, 64 M-rows each
    const int wn   = warp & 1;          // 0..1, 64 N-cols each
    const int g    = lane >> 2;         // 0..7
    const int tg   = lane & 3;          // 0..3

    // staging: thread t owns smem row t for both A and B
    const bool a_ok = (m0 + tid) < M;
    long arow = 0;
    if (a_ok) arow = GATHER_A ? (long)gatherA[e*T_ + m0 + tid] : (long)(m0 + tid);
    const float* Ag = Abase + arow * lda;
    const float* Bg = B + (long)(n0 + tid) * ldb;
    const int asz = a_ok ? 16 : 0;

    const unsigned sA = (unsigned)__cvta_generic_to_shared(As) + tid*ROWSTRIDE*4;
    const unsigned sB = (unsigned)__cvta_generic_to_shared(Bs) + tid*ROWSTRIDE*4;
    const unsigned stageB = STAGE_FLTS*4;

    const int ntiles = K >> 4;

    // prologue: stages 0 and 1
    #pragma unroll
    for (int p = 0; p < PIPE_STAGES-1; p++) {
        const float* ag = Ag + p*16;
        const float* bg = Bg + p*16;
        #pragma unroll
        for (int c = 0; c < 4; c++) {
            cp16(sA + p*stageB + c*16, ag + c*4, asz);
            cp16(sB + p*stageB + c*16, bg + c*4, 16);
        }
        asm volatile("cp.async.commit_group;");
    }

    float acc[2][8][4];
    #pragma unroll
    for (int mt = 0; mt < 2; mt++)
        #pragma unroll
        for (int nt = 0; nt < 8; nt++)
            #pragma unroll
            for (int i = 0; i < 4; i++) acc[mt*1][nt][i] = 0.f;
    // NOTE: warp tile is 64x64 -> mt spans 4 sub-tiles of 16; use acc2 below.
    float acc2[4][8][4];
    #pragma unroll
    for (int mt = 0; mt < 4; mt++)
        #pragma unroll
        for (int nt = 0; nt < 8; nt++)
            #pragma unroll
            for (int i = 0; i < 4; i++) acc2[mt][nt][i] = 0.f;

    for (int kt = 0; kt < ntiles; kt++) {
        asm volatile("cp.async.wait_group %0;" :: "n"(PIPE_STAGES-2));
        __syncthreads();
        const float* a_s = As + (kt % PIPE_STAGES)*STAGE_FLTS;
        const float* b_s = Bs + (kt % PIPE_STAGES)*STAGE_FLTS;

        #pragma unroll
        for (int ks = 0; ks < 16; ks += 8) {
            unsigned a[4][4], b[8][2];
            #pragma unroll
            for (int mt = 0; mt < 4; mt++) {
                int mr = wm*64 + mt*16 + g;
                a[mt][0] = f2tf32(a_s[(mr    )*ROWSTRIDE + ks + tg    ]);
                a[mt][1] = f2tf32(a_s[(mr + 8)*ROWSTRIDE + ks + tg    ]);
                a[mt][2] = f2tf32(a_s[(mr    )*ROWSTRIDE + ks + tg + 4]);
                a[mt][3] = f2tf32(a_s[(mr + 8)*ROWSTRIDE + ks + tg + 4]);
            }
            #pragma unroll
            for (int nt = 0; nt < 8; nt++) {
                int nr = wn*64 + nt*8 + g;
                b[nt][0] = f2tf32(b_s[nr*ROWSTRIDE + ks + tg    ]);
                b[nt][1] = f2tf32(b_s[nr*ROWSTRIDE + ks + tg + 4]);
            }
            #pragma unroll
            for (int mt = 0; mt < 4; mt++)
                #pragma unroll
                for (int nt = 0; nt < 8; nt++)
                    mma_tf32(acc2[mt][nt], a[mt], b[nt]);
        }

        // issue stage kt+2 (empty commit near tail keeps wait_group accounting exact)
        int ktn = kt + PIPE_STAGES - 1;
        if (ktn < ntiles) {
            int st = ktn % PIPE_STAGES;
            const float* ag = Ag + ktn*16;
            const float* bg = Bg + ktn*16;
            #pragma unroll
            for (int c = 0; c < 4; c++) {
                cp16(sA + st*stageB + c*16, ag + c*4, asz);
                cp16(sB + st*stageB + c*16, bg + c*4, 16);
            }
        }
        asm volatile("cp.async.commit_group;");
    }

    // epilogue: c0,c1 -> row g cols 2tg,2tg+1 ; c2,c3 -> row g+8
    #pragma unroll
    for (int mt = 0; mt < 4; mt++) {
        #pragma unroll
        for (int half = 0; half < 2; half++) {
            int lm = m0 + wm*64 + mt*16 + g + half*8;
            if (lm < M) {
                long crow = SCATTER_C ? (long)scatterC[e*T_ + lm] : (long)lm;
                float* Cp = Cbase + crow * ldc + n0 + wn*64 + 2*tg;
                #pragma unroll
                for (int nt = 0; nt < 8; nt++) {
                    float2 v;
                    v.x = acc2[mt][nt][half*2 + 0];
                    v.y = acc2[mt][nt][half*2 + 1];
                    *(float2*)(Cp + nt*8) = v;
                }
            }
        }
    }
    (void)acc;
}

// ---------------- silu-and-mul ----------------
__global__ void silu_shared_kernel() {
    int idx = blockIdx.x * blockDim.x + threadIdx.x;   // over T_*I_/4
    if (idx >= T_*I_/4) return;
    int row = idx / (I_/4);
    int j4  = (idx % (I_/4)) * 4;
    const float4 g = *(const float4*)&d_sgu[(size_t)row*TWOI_ + j4];
    const float4 u = *(const float4*)&d_sgu[(size_t)row*TWOI_ + I_ + j4];
    float4 r;
    r.x = (g.x / (1.f + expf(-g.x))) * u.x;
    r.y = (g.y / (1.f + expf(-g.y))) * u.y;
    r.z = (g.z / (1.f + expf(-g.z))) * u.z;
    r.w = (g.w / (1.f + expf(-g.w))) * u.w;
    *(float4*)&d_sact[(size_t)row*I_ + j4] = r;
}

__global__ void silu_routed_kernel() {
    int idx = blockIdx.x * blockDim.x + threadIdx.x;   // over NPAIR_*I_/4
    if (idx >= NPAIR_*I_/4) return;
    int slot = idx / (I_/4);
    int j4   = (idx % (I_/4)) * 4;
    const float4 g = *(const float4*)&d_gu[(size_t)slot*TWOI_ + j4];
    const float4 u = *(const float4*)&d_gu[(size_t)slot*TWOI_ + I_ + j4];
    float w = d_wslot[slot];
    float4 r;
    r.x = w * (g.x / (1.f + expf(-g.x))) * u.x;
    r.y = w * (g.y / (1.f + expf(-g.y))) * u.y;
    r.z = w * (g.z / (1.f + expf(-g.z))) * u.z;
    r.w = w * (g.w / (1.f + expf(-g.w))) * u.w;
    *(float4*)&d_act[(size_t)slot*I_ + j4] = r;
}

// ---------------- final combine ----------------
__global__ void reduce_kernel(float* __restrict__ out) {
    int idx = blockIdx.x * blockDim.x + threadIdx.x;   // over T_*H_/4
    if (idx >= T_*H_/4) return;
    int t  = idx / (H_/4);
    int h4 = (idx % (H_/4)) * 4;
    float4 s  = *(const float4*)&d_sy[(size_t)t*H_ + h4];
    float4 y0 = *(const float4*)&d_yrt[((size_t)t*TOPK_ + 0)*H_ + h4];
    float4 y1 = *(const float4*)&d_yrt[((size_t)t*TOPK_ + 1)*H_ + h4];
    float4 y2 = *(const float4*)&d_yrt[((size_t)t*TOPK_ + 2)*H_ + h4];
    float4 y3 = *(const float4*)&d_yrt[((size_t)t*TOPK_ + 3)*H_ + h4];
    float4 r;
    r.x = s.x + ROUTED_SCALE_ * (y0.x + y1.x + y2.x + y3.x);
    r.y = s.y + ROUTED_SCALE_ * (y0.y + y1.y + y2.y + y3.y);
    r.z = s.z + ROUTED_SCALE_ * (y0.z + y1.z + y2.z + y3.z);
    r.w = s.w + ROUTED_SCALE_ * (y0.w + y1.w + y2.w + y3.w);
    *(float4*)&out[(size_t)t*H_ + h4] = r;
}

// ---------------- launcher ----------------
extern "C" void kernel_launch(void* const* d_in, const int* in_sizes, int n_in,
                              void* d_out, int out_size) {
    const float* x        = (const float*)d_in[0];  // [T,H]
    const float* gate_w   = (const float*)d_in[1];  // [E,H]
    const float* e_bias   = (const float*)d_in[2];  // [E]
    const float* w_gu     = (const float*)d_in[3];  // [E,2I,H]
    const float* w_dn     = (const float*)d_in[4];  // [E,H,I]
    const float* s_wgu    = (const float*)d_in[5];  // [2I,H]
    const float* s_wdn    = (const float*)d_in[6];  // [H,I]
    float* out = (float*)d_out;

    float *p_gu, *p_act, *p_yrt, *p_sgu, *p_sact, *p_sy;
    int *p_cnt, *p_tok, *p_dst;
    cudaGetSymbolAddress((void**)&p_gu,   d_gu);
    cudaGetSymbolAddress((void**)&p_act,  d_act);
    cudaGetSymbolAddress((void**)&p_yrt,  d_yrt);
    cudaGetSymbolAddress((void**)&p_sgu,  d_sgu);
    cudaGetSymbolAddress((void**)&p_sact, d_sact);
    cudaGetSymbolAddress((void**)&p_sy,   d_sy);
    cudaGetSymbolAddress((void**)&p_cnt,  d_cnt);
    cudaGetSymbolAddress((void**)&p_tok,  d_tok);
    cudaGetSymbolAddress((void**)&p_dst,  d_dst);

    // opt-in to 60KB dynamic smem (idempotent; not a stream op)
    cudaFuncSetAttribute(mma_gemm_tn<false,false,false>,
                         cudaFuncAttributeMaxDynamicSharedMemorySize, SMEM_BYTES);
    cudaFuncSetAttribute(mma_gemm_tn<true,true,true>,
                         cudaFuncAttributeMaxDynamicSharedMemorySize, SMEM_BYTES);

    // 1. reset expert counters
    zero_cnt_kernel<<<1, 32>>>();

    // 2. router + gather-list construction (fp32 exact)
    router_kernel<<<T_, 512>>>(x, gate_w, e_bias);

    // 3. shared expert: gate_up GEMM  [T,H] x [2I,H]^T -> [T,2I]
    mma_gemm_tn<false,false,false><<<dim3(TWOI_/128, T_/128, 1), 128, SMEM_BYTES>>>(
        x, H_, s_wgu, H_, 0, p_sgu, TWOI_, T_, p_cnt, p_tok, p_dst, H_);

    // 4. shared silu*mul
    silu_shared_kernel<<<(T_*I_/4 + 255)/256, 256>>>();

    // 5. shared expert: down GEMM  [T,I] x [H,I]^T -> [T,H]
    mma_gemm_tn<false,false,false><<<dim3(H_/128, T_/128, 1), 128, SMEM_BYTES>>>(
        p_sact, I_, s_wdn, I_, 0, p_sy, H_, T_, p_cnt, p_tok, p_dst, I_);

    // 6. routed gate_up: gather tokens per expert, scatter to pair slots
    mma_gemm_tn<true,true,true><<<dim3(TWOI_/128, T_/128, E_), 128, SMEM_BYTES>>>(
        x, H_, w_gu, H_, (long)TWOI_*H_, p_gu, TWOI_, 0, p_cnt, p_tok, p_dst, H_);

    // 7. routed silu*mul*weight
    silu_routed_kernel<<<(NPAIR_*I_/4 + 255)/256, 256>>>();

    // 8. routed down: gather act rows by slot, scatter outputs by slot
    mma_gemm_tn<true,true,true><<<dim3(H_/128, T_/128, E_), 128, SMEM_BYTES>>>(
        p_act, I_, w_dn, I_, (long)H_*I_, p_yrt, H_, 0, p_cnt, p_dst, p_dst, I_);

    // 9. combine: out = shared + 2.5 * sum_k routed
    reduce_kernel<<<(T_*H_/4 + 255)/256, 256>>>(out);
}